// round 2
// baseline (speedup 1.0000x reference)
#include <cuda_runtime.h>
#include <math.h>

#define NPTS  2048
#define PAIRS 64
#define IVALS 16

// ---- scratch (no allocations allowed) --------------------------------------
__device__ float4 g_y[PAIRS * NPTS];                 // transformed source xyz + |y|^2
__device__ __align__(16) float g_xx[IVALS * NPTS];   // -2 * target.x  (SoA, pair-packable)
__device__ __align__(16) float g_xy[IVALS * NPTS];   // -2 * target.y
__device__ __align__(16) float g_xz[IVALS * NPTS];   // -2 * target.z
__device__ __align__(16) float g_xw[IVALS * NPTS];   // |target|^2
__device__ unsigned g_colmin[PAIRS * NPTS];          // per-(pair,m) min d2, uint-encoded
__device__ float    g_rowpart[PAIRS * 16];           // per-(pair,nsplit) row-min sums

// ---- packed f32x2 helpers ---------------------------------------------------
__device__ __forceinline__ unsigned long long fma2(unsigned long long a,
                                                   unsigned long long b,
                                                   unsigned long long c)
{
    unsigned long long d;
    asm("fma.rn.f32x2 %0, %1, %2, %3;" : "=l"(d) : "l"(a), "l"(b), "l"(c));
    return d;
}
__device__ __forceinline__ unsigned long long add2(unsigned long long a,
                                                   unsigned long long b)
{
    unsigned long long d;
    asm("add.rn.f32x2 %0, %1, %2;" : "=l"(d) : "l"(a), "l"(b));
    return d;
}
__device__ __forceinline__ unsigned long long pack2(float lo, float hi)
{
    unsigned long long d;
    asm("mov.b64 %0, {%1, %2};" : "=l"(d) : "f"(lo), "f"(hi));
    return d;
}
__device__ __forceinline__ void unpack2(unsigned long long v, float& lo, float& hi)
{
    asm("mov.b64 {%0, %1}, %2;" : "=f"(lo), "=f"(hi) : "l"(v));
}

// ---------------------------------------------------------------------------
// Kernel 1: transform source, prescale target into SoA, init colmin.
// Grid: 512 blocks x 256 thr; block = 256 points of one pair.
// Rotation matrix computed ONCE per block (kills the redundant sincosf cost).
// ---------------------------------------------------------------------------
__global__ void prep_kernel(const float* __restrict__ src,
                            const float* __restrict__ tgt,
                            const float* __restrict__ rot,
                            const float* __restrict__ trn,
                            const float* __restrict__ scl)
{
    __shared__ float M[13];
    const int pair = blockIdx.x >> 3;
    const int pbase = (blockIdx.x & 7) * 256;

    if (threadIdx.x == 0) {
        float ax = rot[pair * 3 + 0], ay = rot[pair * 3 + 1], az = rot[pair * 3 + 2];
        float sx, cx, sy, cy, sz, cz;
        sincosf(ax, &sx, &cx);
        sincosf(ay, &sy, &cy);
        sincosf(az, &sz, &cz);
        M[0] = cy * cz;                M[1] = -cy * sz;               M[2] = sy;
        M[3] = cx * sz + sx * sy * cz; M[4] = cx * cz - sx * sy * sz; M[5] = -sx * cy;
        M[6] = sx * sz - cx * sy * cz; M[7] = sx * cz + cx * sy * sz; M[8] = cx * cy;
        M[9]  = trn[pair * 3 + 0];
        M[10] = trn[pair * 3 + 1];
        M[11] = trn[pair * 3 + 2];
        M[12] = scl[pair];
    }
    __syncthreads();

    const int idx = pair * NPTS + pbase + threadIdx.x;
    const float px = src[idx * 3 + 0];
    const float py = src[idx * 3 + 1];
    const float pz = src[idx * 3 + 2];
    const float s = M[12];
    const float qx = s * fmaf(M[0], px, fmaf(M[1], py, fmaf(M[2], pz, M[9])));
    const float qy = s * fmaf(M[3], px, fmaf(M[4], py, fmaf(M[5], pz, M[10])));
    const float qz = s * fmaf(M[6], px, fmaf(M[7], py, fmaf(M[8], pz, M[11])));

    g_y[idx] = make_float4(qx, qy, qz, qx * qx + qy * qy + qz * qz);
    g_colmin[idx] = 0x7F800000u;   // +inf bits

    if (pair < IVALS) {  // targets: only 16 i-slices exist
        const float bx = tgt[idx * 3 + 0];
        const float by = tgt[idx * 3 + 1];
        const float bz = tgt[idx * 3 + 2];
        g_xx[idx] = -2.0f * bx;
        g_xy[idx] = -2.0f * by;
        g_xz[idx] = -2.0f * bz;
        g_xw[idx] = bx * bx + by * by + bz * bz;
    }
}

// ---------------------------------------------------------------------------
// Kernel 2: bidirectional chamfer core, packed f32x2.
// Block (nsplit, pair): 128 target rows x 2048 cols in 16 chunks of 128.
// Thread (tn 0..15, tm 0..15): 8 rows (4 packed pairs) x 8 cols (tm + 16*jj).
//   d2pair = fma2(xz, zd, fma2(xy, yd, fma2(xx, xd, wd_y))) + x2pair
// Both mins operate directly on d2.
// ---------------------------------------------------------------------------
__global__ void __launch_bounds__(256, 2) chamfer_kernel()
{
    const int pair  = blockIdx.y;
    const int nbase = blockIdx.x * 128;
    const int t  = threadIdx.x;
    const int tn = t >> 4;
    const int tm = t & 15;

    __shared__ ulonglong2 s_dxy[128];     // ((yx,yx),(yy,yy)) per col
    __shared__ ulonglong2 s_dzw[128];     // ((yz,yz),(y2,y2)) per col
    __shared__ float s_red[16][129];
    __shared__ float s_sum[8];

    const int xoff = (pair & 15) * NPTS + nbase + tn * 8;
    const float4* gy = g_y + pair * NPTS;
    unsigned* cmin = g_colmin + pair * NPTS;

    unsigned long long xxp[4], xyp[4], xzp[4], xwp[4];
#pragma unroll
    for (int p = 0; p < 4; p++) {
        xxp[p] = *(const unsigned long long*)(g_xx + xoff + 2 * p);
        xyp[p] = *(const unsigned long long*)(g_xy + xoff + 2 * p);
        xzp[p] = *(const unsigned long long*)(g_xz + xoff + 2 * p);
        xwp[p] = *(const unsigned long long*)(g_xw + xoff + 2 * p);
    }

    float rm[8];
#pragma unroll
    for (int i = 0; i < 8; i++) rm[i] = 3.4e38f;

    for (int chunk = 0; chunk < 16; chunk++) {
        const int mbase = chunk * 128;

        __syncthreads();                         // prior chunk's s_d / s_red reads done
        if (t < 128) {
            float4 y = gy[mbase + t];
            s_dxy[t] = make_ulonglong2(pack2(y.x, y.x), pack2(y.y, y.y));
            s_dzw[t] = make_ulonglong2(pack2(y.z, y.z), pack2(y.w, y.w));
        }
        __syncthreads();                         // s_d ready

        float cm[8];
#pragma unroll
        for (int j = 0; j < 8; j++) cm[j] = 3.4e38f;

#pragma unroll
        for (int jj = 0; jj < 8; jj++) {
            const ulonglong2 a = s_dxy[tm + 16 * jj];
            const ulonglong2 b = s_dzw[tm + 16 * jj];
#pragma unroll
            for (int p = 0; p < 4; p++) {
                unsigned long long acc = fma2(xzp[p], b.x, b.y);
                acc = fma2(xyp[p], a.y, acc);
                acc = fma2(xxp[p], a.x, acc);
                unsigned long long d2 = add2(acc, xwp[p]);
                float lo, hi;
                unpack2(d2, lo, hi);
                rm[2 * p]     = fminf(rm[2 * p], lo);
                rm[2 * p + 1] = fminf(rm[2 * p + 1], hi);
                cm[jj] = fminf(cm[jj], lo);
                cm[jj] = fminf(cm[jj], hi);
            }
        }

        // flush col-mins for this chunk
#pragma unroll
        for (int jj = 0; jj < 8; jj++) s_red[tn][tm + 16 * jj] = cm[jj];
        __syncthreads();                         // s_red ready
        if (t < 128) {
            float v = s_red[0][t];
#pragma unroll
            for (int k = 1; k < 16; k++) v = fminf(v, s_red[k][t]);
            v = fmaxf(v, 0.0f);                  // true d2 >= 0: keep uint order monotone
            atomicMin(&cmin[mbase + t], __float_as_uint(v));
        }
    }

    // finalize row mins (rm already holds true d2)
    __syncthreads();
#pragma unroll
    for (int i = 0; i < 8; i++) s_red[tm][tn * 8 + i] = rm[i];
    __syncthreads();

    float total = 0.0f;
    if (t < 128) {
        float v = s_red[0][t];
#pragma unroll
        for (int k = 1; k < 16; k++) v = fminf(v, s_red[k][t]);
        total = v;
    }
#pragma unroll
    for (int off = 16; off > 0; off >>= 1)
        total += __shfl_down_sync(0xffffffffu, total, off);
    if ((t & 31) == 0) s_sum[t >> 5] = total;
    __syncthreads();
    if (t == 0) {
        float acc = s_sum[0] + s_sum[1] + s_sum[2] + s_sum[3] +
                    s_sum[4] + s_sum[5] + s_sum[6] + s_sum[7];
        g_rowpart[pair * 16 + blockIdx.x] = acc;
    }
}

// ---------------------------------------------------------------------------
// Kernel 3: per-pair means and combine
// ---------------------------------------------------------------------------
__global__ void final_kernel(float* __restrict__ out)
{
    const int pair = blockIdx.x;
    const int t = threadIdx.x;
    float local = 0.0f;
#pragma unroll
    for (int k = 0; k < 8; k++)
        local += __uint_as_float(g_colmin[pair * NPTS + t + 256 * k]);
    if (t < 16) local += g_rowpart[pair * 16 + t];

    __shared__ float sbuf[256];
    sbuf[t] = local;
    __syncthreads();
#pragma unroll
    for (int s = 128; s > 0; s >>= 1) {
        if (t < s) sbuf[t] += sbuf[t + s];
        __syncthreads();
    }
    if (t == 0) out[pair] = sbuf[0] * (1.0f / 2048.0f);
}

// ---------------------------------------------------------------------------
extern "C" void kernel_launch(void* const* d_in, const int* in_sizes, int n_in,
                              void* d_out, int out_size)
{
    const float* src = (const float*)d_in[0];   // [4,16,2048,3]
    const float* tgt = (const float*)d_in[1];   // [16,2048,3]
    const float* rot = (const float*)d_in[2];   // [4,16,3]
    const float* trn = (const float*)d_in[3];   // [4,16,3]
    const float* scl = (const float*)d_in[4];   // [4,16]
    (void)in_sizes; (void)n_in; (void)out_size;

    prep_kernel<<<512, 256>>>(src, tgt, rot, trn, scl);
    chamfer_kernel<<<dim3(16, PAIRS), 256>>>();
    final_kernel<<<PAIRS, 256>>>((float*)d_out);
}

// round 3
// speedup vs baseline: 1.2936x; 1.2936x over previous
#include <cuda_runtime.h>
#include <math.h>

#define NPTS  2048
#define PAIRS 64
#define IVALS 16

typedef unsigned long long ull;

// ---- scratch (no allocations allowed) --------------------------------------
__device__ float4 g_y[PAIRS * NPTS];                 // transformed source xyz + |y|^2
__device__ __align__(16) float g_xx[IVALS * NPTS];   // -2 * target.x  (SoA)
__device__ __align__(16) float g_xy[IVALS * NPTS];   // -2 * target.y
__device__ __align__(16) float g_xz[IVALS * NPTS];   // -2 * target.z
__device__ __align__(16) float g_xw[IVALS * NPTS];   // |target|^2
__device__ unsigned g_colmin[PAIRS * NPTS];          // per-(pair,m) min d2, uint bits
__device__ float    g_rowpart[PAIRS * 16];           // per-(pair,nsplit) row-min sums

// ---- packed f32x2 helpers ---------------------------------------------------
__device__ __forceinline__ ull fma2(ull a, ull b, ull c)
{
    ull d;
    asm("fma.rn.f32x2 %0, %1, %2, %3;" : "=l"(d) : "l"(a), "l"(b), "l"(c));
    return d;
}
__device__ __forceinline__ ull add2(ull a, ull b)
{
    ull d;
    asm("add.rn.f32x2 %0, %1, %2;" : "=l"(d) : "l"(a), "l"(b));
    return d;
}
__device__ __forceinline__ ull pack2(float lo, float hi)
{
    ull d;
    asm("mov.b64 %0, {%1, %2};" : "=l"(d) : "f"(lo), "f"(hi));
    return d;
}
__device__ __forceinline__ void unpack2(ull v, float& lo, float& hi)
{
    asm("mov.b64 {%0, %1}, %2;" : "=f"(lo), "=f"(hi) : "l"(v));
}

// ---------------------------------------------------------------------------
// Kernel 1: transform source, prescale target into SoA, init colmin.
// ---------------------------------------------------------------------------
__global__ void prep_kernel(const float* __restrict__ src,
                            const float* __restrict__ tgt,
                            const float* __restrict__ rot,
                            const float* __restrict__ trn,
                            const float* __restrict__ scl)
{
    __shared__ float M[13];
    const int pair = blockIdx.x >> 3;
    const int pbase = (blockIdx.x & 7) * 256;

    if (threadIdx.x == 0) {
        float ax = rot[pair * 3 + 0], ay = rot[pair * 3 + 1], az = rot[pair * 3 + 2];
        float sx, cx, sy, cy, sz, cz;
        sincosf(ax, &sx, &cx);
        sincosf(ay, &sy, &cy);
        sincosf(az, &sz, &cz);
        M[0] = cy * cz;                M[1] = -cy * sz;               M[2] = sy;
        M[3] = cx * sz + sx * sy * cz; M[4] = cx * cz - sx * sy * sz; M[5] = -sx * cy;
        M[6] = sx * sz - cx * sy * cz; M[7] = sx * cz + cx * sy * sz; M[8] = cx * cy;
        M[9]  = trn[pair * 3 + 0];
        M[10] = trn[pair * 3 + 1];
        M[11] = trn[pair * 3 + 2];
        M[12] = scl[pair];
    }
    __syncthreads();

    const int idx = pair * NPTS + pbase + threadIdx.x;
    const float px = src[idx * 3 + 0];
    const float py = src[idx * 3 + 1];
    const float pz = src[idx * 3 + 2];
    const float s = M[12];
    const float qx = s * fmaf(M[0], px, fmaf(M[1], py, fmaf(M[2], pz, M[9])));
    const float qy = s * fmaf(M[3], px, fmaf(M[4], py, fmaf(M[5], pz, M[10])));
    const float qz = s * fmaf(M[6], px, fmaf(M[7], py, fmaf(M[8], pz, M[11])));

    g_y[idx] = make_float4(qx, qy, qz, qx * qx + qy * qy + qz * qz);
    g_colmin[idx] = 0x7F800000u;   // +inf bits

    if (pair < IVALS) {
        const float bx = tgt[idx * 3 + 0];
        const float by = tgt[idx * 3 + 1];
        const float bz = tgt[idx * 3 + 2];
        g_xx[idx] = -2.0f * bx;
        g_xy[idx] = -2.0f * by;
        g_xz[idx] = -2.0f * bz;
        g_xw[idx] = bx * bx + by * by + bz * bz;
    }
}

// ---------------------------------------------------------------------------
// Kernel 2: bidirectional chamfer, f32x2 packed over the COLUMN (y) axis.
// Block (nsplit, pair): 128 x-rows (registers, dup-packed) x 2048 y-cols
// streamed via shared SoA in 16 chunks of 128. Thread tile: 8 rows x 8 cols
// (4 packed column pairs).
//   c  = fma2(xx,yx, fma2(xy,yy, fma2(xz,yz, yw)))   // = |y|^2 - 2 x.y (2 cols)
//   d2 = add2(c, x2dup)                              // full distance (2 cols)
// rowmin over c (x2 deferred to finalize), colmin over d2.
// ---------------------------------------------------------------------------
__global__ void __launch_bounds__(256, 2) chamfer_kernel()
{
    const int pair  = blockIdx.y;
    const int nbase = blockIdx.x * 128;
    const int t  = threadIdx.x;
    const int tn = t >> 4;
    const int tm = t & 15;

    __shared__ __align__(16) float s_yx[128];
    __shared__ __align__(16) float s_yy[128];
    __shared__ __align__(16) float s_yz[128];
    __shared__ __align__(16) float s_yw[128];
    __shared__ float s_red[16][129];
    __shared__ float s_sum[8];

    const int xoff = (pair & 15) * NPTS + nbase + tn * 8;
    const float4* gy = g_y + pair * NPTS;
    unsigned* cmin = g_colmin + pair * NPTS;

    // dup-packed x operands, loaded once (setup cost amortized over 16 chunks)
    ull xxp[8], xyp[8], xzp[8], xwp[8];
#pragma unroll
    for (int i = 0; i < 8; i++) {
        float vx = g_xx[xoff + i];
        float vy = g_xy[xoff + i];
        float vz = g_xz[xoff + i];
        float vw = g_xw[xoff + i];
        xxp[i] = pack2(vx, vx);
        xyp[i] = pack2(vy, vy);
        xzp[i] = pack2(vz, vz);
        xwp[i] = pack2(vw, vw);
    }

    float rm[8];
#pragma unroll
    for (int i = 0; i < 8; i++) rm[i] = 3.4e38f;

    for (int chunk = 0; chunk < 16; chunk++) {
        const int mbase = chunk * 128;

        __syncthreads();                     // prior chunk's shared reads done
        if (t < 128) {
            float4 y = gy[mbase + t];
            s_yx[t] = y.x;
            s_yy[t] = y.y;
            s_yz[t] = y.z;
            s_yw[t] = y.w;
        }
        __syncthreads();                     // SoA ready

        float cmlo[4], cmhi[4];
#pragma unroll
        for (int g = 0; g < 4; g++) { cmlo[g] = 3.4e38f; cmhi[g] = 3.4e38f; }

#pragma unroll
        for (int g = 0; g < 4; g++) {
            const int cp = tm * 2 + 32 * g;          // even column index
            const ull yx = *(const ull*)(s_yx + cp); // (y_j, y_{j+1}) packed
            const ull yy = *(const ull*)(s_yy + cp);
            const ull yz = *(const ull*)(s_yz + cp);
            const ull yw = *(const ull*)(s_yw + cp);
#pragma unroll
            for (int i = 0; i < 8; i++) {
                ull c = fma2(xzp[i], yz, yw);
                c = fma2(xyp[i], yy, c);
                c = fma2(xxp[i], yx, c);
                ull d2 = add2(c, xwp[i]);
                float clo, chi, dlo, dhi;
                unpack2(c, clo, chi);
                unpack2(d2, dlo, dhi);
                rm[i]   = fminf(rm[i], fminf(clo, chi));
                cmlo[g] = fminf(cmlo[g], dlo);
                cmhi[g] = fminf(cmhi[g], dhi);
            }
        }

        // flush col-mins for this chunk: reduce over tn, then atomicMin
#pragma unroll
        for (int g = 0; g < 4; g++) {
            s_red[tn][tm * 2 + 32 * g]     = cmlo[g];
            s_red[tn][tm * 2 + 1 + 32 * g] = cmhi[g];
        }
        __syncthreads();
        if (t < 128) {
            float v = s_red[0][t];
#pragma unroll
            for (int k = 1; k < 16; k++) v = fminf(v, s_red[k][t]);
            v = fmaxf(v, 0.0f);              // d2 >= 0: keep uint ordering monotone
            atomicMin(&cmin[mbase + t], __float_as_uint(v));
        }
    }

    // finalize row mins: add deferred x2, reduce over tm
    __syncthreads();
#pragma unroll
    for (int i = 0; i < 8; i++) {
        float x2lo, x2hi;
        unpack2(xwp[i], x2lo, x2hi);
        s_red[tm][tn * 8 + i] = rm[i] + x2lo;
    }
    __syncthreads();

    float total = 0.0f;
    if (t < 128) {
        float v = s_red[0][t];
#pragma unroll
        for (int k = 1; k < 16; k++) v = fminf(v, s_red[k][t]);
        total = v;
    }
#pragma unroll
    for (int off = 16; off > 0; off >>= 1)
        total += __shfl_down_sync(0xffffffffu, total, off);
    if ((t & 31) == 0) s_sum[t >> 5] = total;
    __syncthreads();
    if (t == 0) {
        float acc = s_sum[0] + s_sum[1] + s_sum[2] + s_sum[3] +
                    s_sum[4] + s_sum[5] + s_sum[6] + s_sum[7];
        g_rowpart[pair * 16 + blockIdx.x] = acc;
    }
}

// ---------------------------------------------------------------------------
// Kernel 3: per-pair means and combine
// ---------------------------------------------------------------------------
__global__ void final_kernel(float* __restrict__ out)
{
    const int pair = blockIdx.x;
    const int t = threadIdx.x;
    float local = 0.0f;
#pragma unroll
    for (int k = 0; k < 8; k++)
        local += __uint_as_float(g_colmin[pair * NPTS + t + 256 * k]);
    if (t < 16) local += g_rowpart[pair * 16 + t];

    __shared__ float sbuf[256];
    sbuf[t] = local;
    __syncthreads();
#pragma unroll
    for (int s = 128; s > 0; s >>= 1) {
        if (t < s) sbuf[t] += sbuf[t + s];
        __syncthreads();
    }
    if (t == 0) out[pair] = sbuf[0] * (1.0f / 2048.0f);
}

// ---------------------------------------------------------------------------
extern "C" void kernel_launch(void* const* d_in, const int* in_sizes, int n_in,
                              void* d_out, int out_size)
{
    const float* src = (const float*)d_in[0];   // [4,16,2048,3]
    const float* tgt = (const float*)d_in[1];   // [16,2048,3]
    const float* rot = (const float*)d_in[2];   // [4,16,3]
    const float* trn = (const float*)d_in[3];   // [4,16,3]
    const float* scl = (const float*)d_in[4];   // [4,16]
    (void)in_sizes; (void)n_in; (void)out_size;

    prep_kernel<<<512, 256>>>(src, tgt, rot, trn, scl);
    chamfer_kernel<<<dim3(16, PAIRS), 256>>>();
    final_kernel<<<PAIRS, 256>>>((float*)d_out);
}